// round 2
// baseline (speedup 1.0000x reference)
#include <cuda_runtime.h>
#include <cstdint>

// Problem constants (from reference)
#define NRAYS_MAX   131072
#define MAX_PTS     128
#define GRID_R      128
#define OCC_ELEMS   (GRID_R * GRID_R * GRID_R)        // 2097152
#define OCC_WORDS   (OCC_ELEMS / 32)                  // 65536 words = 256 KB

__device__ uint32_t g_occ_bits[OCC_WORDS];
__device__ float    g_eff_near[NRAYS_MAX];
__device__ int      g_flag_wide;   // saw a byte value > 1  -> float-coded elements
__device__ int      g_flag_off;    // saw byte==1 at offset%4 != 0 -> 1-byte bools

// ---------------------------------------------------------------------------
// Kernel 0: dtype detection. Scans the first 2 MB (safe under every dtype
// hypothesis: bool->2MB, int32/float32->8MB). Single block; plain final store
// keeps it deterministic across graph replays.
// ---------------------------------------------------------------------------
__global__ void detect_occ_kernel(const uint8_t* __restrict__ occ) {
    __shared__ int s_wide, s_off;
    if (threadIdx.x == 0) { s_wide = 0; s_off = 0; }
    __syncthreads();

    int wide = 0, off = 0;
    const uint4* p = reinterpret_cast<const uint4*>(occ);
    // 2 MB = 131072 uint4
    for (int i = threadIdx.x; i < 131072; i += blockDim.x) {
        uint4 v = p[i];
        uint32_t ws[4] = {v.x, v.y, v.z, v.w};
#pragma unroll
        for (int q = 0; q < 4; q++) {
            uint32_t wv = ws[q];
#pragma unroll
            for (int k = 0; k < 4; k++) {
                uint32_t b = (wv >> (8 * k)) & 0xffu;
                wide |= (b > 1u);
                if (k > 0) off |= (b == 1u);
            }
        }
    }
    if (wide) atomicOr(&s_wide, 1);
    if (off)  atomicOr(&s_off, 1);
    __syncthreads();
    if (threadIdx.x == 0) { g_flag_wide = s_wide; g_flag_off = s_off; }
}

// ---------------------------------------------------------------------------
// Kernel 1: pack occupancy into a 256 KB bit grid, dtype-adaptive.
//   stride-4 (float32 or int32): bit = (32-bit word != 0)
//   stride-1 (bool bytes)      : bit = (byte != 0)
// One thread per output word (32 elements).
// ---------------------------------------------------------------------------
__global__ void pack_occ_kernel(const uint8_t* __restrict__ occ) {
    int w = blockIdx.x * blockDim.x + threadIdx.x;
    if (w >= OCC_WORDS) return;

    bool stride4 = g_flag_wide || !g_flag_off;
    uint32_t bits = 0;

    if (stride4) {
        // 32 elements * 4 bytes = 128 B = 8 uint4
        const uint4* p = reinterpret_cast<const uint4*>(occ) + (size_t)w * 8;
#pragma unroll
        for (int i = 0; i < 8; i++) {
            uint4 v = p[i];
            if (v.x) bits |= 1u << (i * 4 + 0);
            if (v.y) bits |= 1u << (i * 4 + 1);
            if (v.z) bits |= 1u << (i * 4 + 2);
            if (v.w) bits |= 1u << (i * 4 + 3);
        }
    } else {
        // 32 elements * 1 byte = 32 B = 2 uint4
        const uint4* p = reinterpret_cast<const uint4*>(occ) + (size_t)w * 2;
        uint4 a = p[0];
        uint4 b = p[1];
        uint32_t v[8] = {a.x, a.y, a.z, a.w, b.x, b.y, b.z, b.w};
#pragma unroll
        for (int i = 0; i < 8; i++) {
            uint32_t x = v[i];
#pragma unroll
            for (int k = 0; k < 4; k++) {
                if ((x >> (8 * k)) & 0xffu) bits |= 1u << (i * 4 + k);
            }
        }
    }
    g_occ_bits[w] = bits;
}

// ---------------------------------------------------------------------------
// Kernel 2: empty-space-skipping ray march. One thread per ray.
// Replicates reference arithmetic:
//   t_next = t + STEP                       (fp32 add)
//   p      = o + d * t_next                 (separate mul + add, no fma)
//   idx    = (int)((p - aabb_min) / cell)   (IEEE div, C truncation)
// hit  -> new_near = min(t_next, FAR), stop
// past (t_next > FAR, no hit) -> new_near = FAR, stop
// ---------------------------------------------------------------------------
__global__ void march_kernel(const float* __restrict__ ro,
                             const float* __restrict__ rd,
                             int n) {
    int r = blockIdx.x * blockDim.x + threadIdx.x;
    if (r >= n) return;

    const float NEARF = 2.0f;
    const float FARF  = 6.0f;
    const float CELL  = 0.0234375f;   // 3/128 exact
    const float AMIN  = -1.5f;
    // numpy: STEP = float32(0.5 * norm(cell_f32)); 27/16384 exact in fp32,
    // sqrt correctly rounded, *0.5 exact -> bit-identical STEP.
    const float STEP = 0.5f * __fsqrt_rn(0.00164794921875f);

    float ox = ro[3 * r + 0], oy = ro[3 * r + 1], oz = ro[3 * r + 2];
    float dx = rd[3 * r + 0], dy = rd[3 * r + 1], dz = rd[3 * r + 2];

    float t  = NEARF;
    float nn = NEARF;

#pragma unroll 1
    for (int k = 0; k < 200; k++) {   // MAX_STEPS = ceil(4/STEP)+2 = 200
        float tn = __fadd_rn(t, STEP);
        float px = __fadd_rn(ox, __fmul_rn(dx, tn));
        float py = __fadd_rn(oy, __fmul_rn(dy, tn));
        float pz = __fadd_rn(oz, __fmul_rn(dz, tn));
        int ix = (int)__fdiv_rn(__fsub_rn(px, AMIN), CELL);
        int iy = (int)__fdiv_rn(__fsub_rn(py, AMIN), CELL);
        int iz = (int)__fdiv_rn(__fsub_rn(pz, AMIN), CELL);

        bool valid = ((unsigned)ix < (unsigned)GRID_R) &
                     ((unsigned)iy < (unsigned)GRID_R) &
                     ((unsigned)iz < (unsigned)GRID_R);
        bool hit = false;
        if (valid) {
            int li = (ix << 14) | (iy << 7) | iz;
            hit = (g_occ_bits[li >> 5] >> (li & 31)) & 1u;
        }
        if (hit)       { nn = fminf(tn, FARF); break; }
        if (tn > FARF) { nn = FARF;            break; }
        t = tn;
    }
    g_eff_near[r] = fminf(nn, FARF);
}

// ---------------------------------------------------------------------------
// Kernel 3: stratified sampling. One thread per (ray, sample).
// z_j = near*(1-t_j) + FAR*t_j, t_j = linspace(0,1,128);
// lower/upper via midpoints; z = lower + (upper-lower)*t_rand;
// pts = o + d*z. Output layout: pts [n*128*3] then z [n*128].
// ---------------------------------------------------------------------------
__device__ __forceinline__ float z_at(float near_v, int jj) {
    const float FARF = 6.0f;
    float t = (jj >= 127) ? 1.0f : (float)jj * (1.0f / 127.0f);
    return near_v * (1.0f - t) + FARF * t;
}

__global__ void sample_kernel(const float* __restrict__ ro,
                              const float* __restrict__ rd,
                              const float* __restrict__ trand,
                              float* __restrict__ out,
                              int n) {
    int gid = blockIdx.x * blockDim.x + threadIdx.x;
    int total = n * MAX_PTS;
    if (gid >= total) return;

    int r = gid >> 7;
    int j = gid & 127;

    float near_v = g_eff_near[r];
    float zj = z_at(near_v, j);

    float lower, upper;
    if (j == 0) {
        lower = zj;
    } else {
        lower = 0.5f * (z_at(near_v, j - 1) + zj);
    }
    if (j == 127) {
        upper = zj;
    } else {
        upper = 0.5f * (zj + z_at(near_v, j + 1));
    }

    float z = lower + (upper - lower) * trand[gid];

    float ox = ro[3 * r + 0], oy = ro[3 * r + 1], oz = ro[3 * r + 2];
    float dx = rd[3 * r + 0], dy = rd[3 * r + 1], dz = rd[3 * r + 2];

    size_t pbase = (size_t)gid * 3;
    out[pbase + 0] = ox + dx * z;
    out[pbase + 1] = oy + dy * z;
    out[pbase + 2] = oz + dz * z;
    out[(size_t)total * 3 + gid] = z;
}

// ---------------------------------------------------------------------------
extern "C" void kernel_launch(void* const* d_in, const int* in_sizes, int n_in,
                              void* d_out, int out_size) {
    const float*   ro  = (const float*)d_in[0];   // rays_o   [n,3]
    const float*   rd  = (const float*)d_in[1];   // viewdirs [n,3]
    const float*   tr  = (const float*)d_in[2];   // t_rand   [n,128]
    const uint8_t* occ = (const uint8_t*)d_in[3]; // occ_grid [128^3], dtype unknown

    int n = in_sizes[0] / 3;
    int total = n * MAX_PTS;

    detect_occ_kernel<<<1, 512>>>(occ);
    pack_occ_kernel<<<OCC_WORDS / 256, 256>>>(occ);
    march_kernel<<<(n + 255) / 256, 256>>>(ro, rd, n);
    sample_kernel<<<(total + 255) / 256, 256>>>(ro, rd, tr, (float*)d_out, n);
}

// round 3
// speedup vs baseline: 2.4313x; 2.4313x over previous
#include <cuda_runtime.h>
#include <cstdint>

#define NRAYS_MAX   131072
#define MAX_PTS     128
#define GRID_R      128
#define OCC_WORDS   (GRID_R * GRID_R * GRID_R / 32)   // 65536 words = 256 KB
#define NSTEPS      200

__device__ uint32_t g_occ_bits[OCC_WORDS];
__device__ float    g_eff_near[NRAYS_MAX];
__device__ float    g_T[130];     // T[j] = smallest s with trunc(RN(s/CELL)) >= j, j=0..128
__device__ float    g_tn[NSTEPS]; // exact fp32 fold of t += STEP starting at 2.0

// ---------------------------------------------------------------------------
// Kernel 0: build exact division-breakpoint table + tn sequence.
// T[j] for j>=1: smallest s with RN(s/CELL) >= j  (trunc>=j for q>=0).
// T[0]:          smallest s with RN(s/CELL) > -1  (trunc(q) >= 0, toward-zero).
// Uses __fdiv_rn as the oracle -> marching becomes bit-exact without divides.
// ---------------------------------------------------------------------------
__global__ void setup_kernel() {
    const float CELL = 0.0234375f;     // 3/128 exact
    int i = threadIdx.x;

    if (i == 0) {
        // numpy: STEP = fp32(0.5*norm(cell)); 27/16384 exact, sqrt RN -> exact STEP
        const float STEP = 0.5f * __fsqrt_rn(0.00164794921875f);
        float t = 2.0f;
        for (int k = 0; k < NSTEPS; k++) { t = __fadd_rn(t, STEP); g_tn[k] = t; }
    }

    if (i <= 128) {
        float s;
        if (i == 0) {
            s = -CELL;                                // q(-CELL) = -1 exactly -> pred false
            while (!(__fdiv_rn(s, CELL) > -1.0f)) s = nextafterf(s, 1e30f);
        } else {
            float j = (float)i;
            s = __fmul_rn(j, CELL);
            if (__fdiv_rn(s, CELL) >= j) {
                float s2 = nextafterf(s, -1e30f);
                while (__fdiv_rn(s2, CELL) >= j) { s = s2; s2 = nextafterf(s, -1e30f); }
            } else {
                while (!(__fdiv_rn(s, CELL) >= j)) s = nextafterf(s, 1e30f);
            }
        }
        g_T[i] = s;
    }
}

// ---------------------------------------------------------------------------
// Kernel 1: pack occupancy (4-byte elements, bit = word != 0) into bit grid.
// ---------------------------------------------------------------------------
__global__ void pack_occ_kernel(const uint8_t* __restrict__ occ) {
    int w = blockIdx.x * blockDim.x + threadIdx.x;
    if (w >= OCC_WORDS) return;
    const uint4* p = reinterpret_cast<const uint4*>(occ) + (size_t)w * 8;
    uint32_t bits = 0;
#pragma unroll
    for (int i = 0; i < 8; i++) {
        uint4 v = p[i];
        if (v.x) bits |= 1u << (i * 4 + 0);
        if (v.y) bits |= 1u << (i * 4 + 1);
        if (v.z) bits |= 1u << (i * 4 + 2);
        if (v.w) bits |= 1u << (i * 4 + 3);
    }
    g_occ_bits[w] = bits;
}

// ---------------------------------------------------------------------------
// Kernel 2: ray march, divide-free. One thread per ray.
// Per step (exact vs reference):
//   tn from precomputed fold table;
//   p = o + d*tn (separate RN mul/add);  s = p + 1.5 (== p - aabb_min);
//   idx via breakpoint table (bit-exact trunc(RN(s/CELL)));
// hit -> nn = min(tn, FAR) stop; past (tn>FAR, no hit) -> FAR stop.
// ---------------------------------------------------------------------------
__device__ __forceinline__ int idx_from_s(float s, const float* __restrict__ T,
                                          bool& inv) {
    const float INV_CELL = 42.666668f;          // RN(128/3), approx only
    inv = (s < T[0]) | (s >= T[128]);
    int j = (int)floorf(__fmul_rn(s, INV_CELL));
    j = min(max(j, 0), 127);
    j += (s >= T[j + 1]);
    j -= (s < T[j]);
    return j;
}

__global__ void march_kernel(const float* __restrict__ ro,
                             const float* __restrict__ rd,
                             int n) {
    __shared__ float sT[130];
    __shared__ float sTn[NSTEPS];
    for (int i = threadIdx.x; i < 130; i += blockDim.x) sT[i] = g_T[i];
    for (int i = threadIdx.x; i < NSTEPS; i += blockDim.x) sTn[i] = g_tn[i];
    __syncthreads();

    int r = blockIdx.x * blockDim.x + threadIdx.x;
    if (r >= n) return;

    const float FARF = 6.0f;

    float ox = ro[3 * r + 0], oy = ro[3 * r + 1], oz = ro[3 * r + 2];
    float dx = rd[3 * r + 0], dy = rd[3 * r + 1], dz = rd[3 * r + 2];

    float nn = 2.0f;   // new_near init = NEAR

#pragma unroll 1
    for (int k0 = 0; k0 < NSTEPS; k0 += 4) {
        bool hitv[4], pastv[4];
        float tnv[4];
#pragma unroll
        for (int u = 0; u < 4; u++) {
            float tn = sTn[k0 + u];
            tnv[u] = tn;
            float sx = __fadd_rn(__fadd_rn(ox, __fmul_rn(dx, tn)), 1.5f);
            float sy = __fadd_rn(__fadd_rn(oy, __fmul_rn(dy, tn)), 1.5f);
            float sz = __fadd_rn(__fadd_rn(oz, __fmul_rn(dz, tn)), 1.5f);
            bool ivx, ivy, ivz;
            int jx = idx_from_s(sx, sT, ivx);
            int jy = idx_from_s(sy, sT, ivy);
            int jz = idx_from_s(sz, sT, ivz);
            bool valid = !(ivx | ivy | ivz);
            bool hit = false;
            if (valid) {
                int li = (jx << 14) | (jy << 7) | jz;
                hit = (g_occ_bits[li >> 5] >> (li & 31)) & 1u;
            }
            hitv[u] = hit;
            pastv[u] = (tn > FARF);
        }
        bool done = false;
#pragma unroll
        for (int u = 0; u < 4; u++) {
            if (!done) {
                if (hitv[u])       { nn = fminf(tnv[u], FARF); done = true; }
                else if (pastv[u]) { nn = FARF;                done = true; }
            }
        }
        if (done) break;
    }
    g_eff_near[r] = fminf(nn, FARF);
}

// ---------------------------------------------------------------------------
// Kernel 3: stratified sampling. One block (128 thr) per ray.
// Phase 1: thread j computes z_j (same formulas as before), stages in smem,
//          writes z output coalesced.
// Phase 2: 96 threads emit the ray's 384 pts floats as coalesced float4s.
// ---------------------------------------------------------------------------
__device__ __forceinline__ float z_at(float near_v, int jj) {
    const float FARF = 6.0f;
    float t = (jj >= 127) ? 1.0f : (float)jj * (1.0f / 127.0f);
    return near_v * (1.0f - t) + FARF * t;
}

__global__ void sample_kernel(const float* __restrict__ ro,
                              const float* __restrict__ rd,
                              const float* __restrict__ trand,
                              float* __restrict__ out,
                              int n) {
    __shared__ float zsh[MAX_PTS];
    __shared__ float odsh[6];

    int r = blockIdx.x;
    int j = threadIdx.x;

    if (j < 3)               odsh[j]     = ro[3 * r + j];
    else if (j < 6)          odsh[j]     = rd[3 * r + (j - 3)];
    float near_v = g_eff_near[r];

    // z_j
    float zj = z_at(near_v, j);
    float lower = (j == 0)   ? zj : 0.5f * (z_at(near_v, j - 1) + zj);
    float upper = (j == 127) ? zj : 0.5f * (zj + z_at(near_v, j + 1));
    float z = lower + (upper - lower) * trand[(size_t)r * MAX_PTS + j];
    zsh[j] = z;

    // z output: [total*3 .. total*4)
    size_t total = (size_t)n * MAX_PTS;
    out[total * 3 + (size_t)r * MAX_PTS + j] = z;
    __syncthreads();

    // pts output: 384 floats for this ray as 96 float4 stores
    if (j < 96) {
        float4 v;
        int f0 = 4 * j;   // float index within ray's pts block
        float comp[4];
#pragma unroll
        for (int m = 0; m < 4; m++) {
            int f = f0 + m;
            int sidx = f / 3;
            int c = f - 3 * sidx;
            comp[m] = odsh[c] + odsh[3 + c] * zsh[sidx];
        }
        v.x = comp[0]; v.y = comp[1]; v.z = comp[2]; v.w = comp[3];
        reinterpret_cast<float4*>(out)[(size_t)r * 96 + j] = v;
    }
}

// ---------------------------------------------------------------------------
extern "C" void kernel_launch(void* const* d_in, const int* in_sizes, int n_in,
                              void* d_out, int out_size) {
    const float*   ro  = (const float*)d_in[0];   // rays_o   [n,3]
    const float*   rd  = (const float*)d_in[1];   // viewdirs [n,3]
    const float*   tr  = (const float*)d_in[2];   // t_rand   [n,128]
    const uint8_t* occ = (const uint8_t*)d_in[3]; // occ_grid [128^3], 4B elems

    int n = in_sizes[0] / 3;

    setup_kernel<<<1, 256>>>();
    pack_occ_kernel<<<OCC_WORDS / 256, 256>>>(occ);
    march_kernel<<<(n + 127) / 128, 128>>>(ro, rd, n);
    sample_kernel<<<n, 128>>>(ro, rd, tr, (float*)d_out, n);
}

// round 5
// speedup vs baseline: 4.6825x; 1.9259x over previous
#include <cuda_runtime.h>
#include <cstdint>

#define NRAYS_MAX   131072
#define MAX_PTS     128
#define GRID_R      128
#define OCC_WORDS   (GRID_R * GRID_R * GRID_R / 32)   // 65536 words = 256 KB
#define NSTEPS      200

__device__ uint32_t g_occ_bits[OCC_WORDS];
__device__ float    g_eff_near[NRAYS_MAX];
__device__ float    g_tn[NSTEPS];   // exact fp32 fold of t += STEP from 2.0

// ---------------------------------------------------------------------------
// Kernel 0: build the exact tn sequence (serial fp32 fold, bit-identical to
// the reference's t += STEP chain). STEP = fp32(0.5*sqrt(27/16384)) exact.
// ---------------------------------------------------------------------------
__global__ void setup_kernel() {
    const float STEP = 0.5f * __fsqrt_rn(0.00164794921875f);
    float t = 2.0f;
    for (int k = 0; k < NSTEPS; k++) { t = __fadd_rn(t, STEP); g_tn[k] = t; }
}

// ---------------------------------------------------------------------------
// Kernel 1: pack occupancy (4-byte elements, bit = word != 0) into bit grid.
// ---------------------------------------------------------------------------
__global__ void pack_occ_kernel(const uint8_t* __restrict__ occ) {
    int w = blockIdx.x * blockDim.x + threadIdx.x;
    if (w >= OCC_WORDS) return;
    const uint4* p = reinterpret_cast<const uint4*>(occ) + (size_t)w * 8;
    uint32_t bits = 0;
#pragma unroll
    for (int i = 0; i < 8; i++) {
        uint4 v = p[i];
        if (v.x) bits |= 1u << (i * 4 + 0);
        if (v.y) bits |= 1u << (i * 4 + 1);
        if (v.z) bits |= 1u << (i * 4 + 2);
        if (v.w) bits |= 1u << (i * 4 + 3);
    }
    g_occ_bits[w] = bits;
}

// ---------------------------------------------------------------------------
// voxel index: trunc(RN(s/CELL)) with CELL = 3/128 = 3 * 2^-7.
// RN(s/CELL) = RN(s/3) * 128 exactly (power-of-2 scaling commutes with RN).
// RN(s/3) via Markstein two-FMA refinement (y = RN(1/3) correctly rounded,
// q0 within 1 ulp, exact fma residual) -> correctly rounded quotient,
// bit-identical to __fdiv_rn. (int) cast truncates toward zero, matching
// numpy astype(int32): s in (-CELL, 0) -> idx 0 (VALID).
// ---------------------------------------------------------------------------
__device__ __forceinline__ int vox_idx(float s) {
    const float THIRD = 0.33333334f;            // RN(1/3)
    float q0 = __fmul_rn(s, THIRD);
    float rr = __fmaf_rn(-3.0f, q0, s);
    float q  = __fmaf_rn(rr, THIRD, q0);
    return (int)__fmul_rn(q, 128.0f);
}

// ---------------------------------------------------------------------------
// Kernel 2: divide-free ray march with AABB entry skip + exit early-out.
// CRITICAL: truncation-toward-zero makes the valid region the box expanded
// by one CELL on every negative face: p in (-1.5-CELL, +1.5) per axis.
// Slab test uses those expanded bounds, with 3-step margins on both ends.
// ---------------------------------------------------------------------------
__global__ void march_kernel(const float* __restrict__ ro,
                             const float* __restrict__ rd,
                             int n) {
    __shared__ float sTn[NSTEPS];
    for (int i = threadIdx.x; i < NSTEPS; i += blockDim.x) sTn[i] = g_tn[i];
    __syncthreads();

    int r = blockIdx.x * blockDim.x + threadIdx.x;
    if (r >= n) return;

    const float FARF = 6.0f;
    const float CELL = 0.0234375f;
    const float STEP = 0.5f * __fsqrt_rn(0.00164794921875f);
    const float BMIN = -1.5f - CELL;   // truncation-expanded negative faces
    const float BMAX =  1.5f;          // exact: idx<=127 requires s < 3.0

    float ox = ro[3 * r + 0], oy = ro[3 * r + 1], oz = ro[3 * r + 2];
    float dx = rd[3 * r + 0], dy = rd[3 * r + 1], dz = rd[3 * r + 2];

    // slab test on the EXPANDED box (approximate; 3-step margins both ends)
    float t_lo = 0.0f, t_hi = 1e30f;
    {
        float o[3] = {ox, oy, oz}, d[3] = {dx, dy, dz};
#pragma unroll
        for (int a = 0; a < 3; a++) {
            if (fabsf(d[a]) > 1e-8f) {
                float inv = __frcp_rn(d[a]);
                float t1 = (BMIN - o[a]) * inv;
                float t2 = (BMAX - o[a]) * inv;
                t_lo = fmaxf(t_lo, fminf(t1, t2));
                t_hi = fminf(t_hi, fmaxf(t1, t2));
            } else if (o[a] < BMIN - 0.001f || o[a] > BMAX + 0.001f) {
                t_lo = 1e30f;   // parallel and strictly outside -> never valid
            }
        }
    }
    int k_start = (int)floorf((t_lo - 2.0f) / STEP) - 3;
    k_start = max(k_start, 0);
    k_start = min(k_start, 196);
    k_start &= ~3;                          // align to unroll-4 blocks
    float limit = fminf(FARF, t_hi + 3.0f * STEP);

    float nn = 2.0f;

#pragma unroll 1
    for (int k0 = k_start; k0 < NSTEPS; k0 += 4) {
        bool hitv[4], pastv[4];
        float tnv[4];
#pragma unroll
        for (int u = 0; u < 4; u++) {
            float tn = sTn[k0 + u];
            tnv[u] = tn;
            float sx = __fadd_rn(__fadd_rn(ox, __fmul_rn(dx, tn)), 1.5f);
            float sy = __fadd_rn(__fadd_rn(oy, __fmul_rn(dy, tn)), 1.5f);
            float sz = __fadd_rn(__fadd_rn(oz, __fmul_rn(dz, tn)), 1.5f);
            int jx = vox_idx(sx);
            int jy = vox_idx(sy);
            int jz = vox_idx(sz);
            bool valid = ((unsigned)jx < 128u) & ((unsigned)jy < 128u) &
                         ((unsigned)jz < 128u);
            bool hit = false;
            if (valid) {
                int li = (jx << 14) | (jy << 7) | jz;
                hit = (g_occ_bits[li >> 5] >> (li & 31)) & 1u;
            }
            hitv[u]  = hit;
            pastv[u] = (tn > limit);
        }
        bool done = false;
#pragma unroll
        for (int u = 0; u < 4; u++) {
            if (!done) {
                if (hitv[u])       { nn = fminf(tnv[u], FARF); done = true; }
                else if (pastv[u]) { nn = FARF;                done = true; }
            }
        }
        if (done) break;
    }
    g_eff_near[r] = fminf(nn, FARF);
}

// ---------------------------------------------------------------------------
// Kernel 3: stratified sampling, warp-per-ray. 512-thread blocks (16 rays).
// Lane computes 4 consecutive z (float4 t_rand load, float4 z store), stages
// z in smem, __syncwarp, then each lane emits 3 coalesced float4 pts stores.
// ---------------------------------------------------------------------------
__device__ __forceinline__ float z_at(float near_v, int jj) {
    float t = (jj >= 127) ? 1.0f : (float)jj * (1.0f / 127.0f);
    return near_v * (1.0f - t) + 6.0f * t;
}

__global__ void sample_kernel(const float* __restrict__ ro,
                              const float* __restrict__ rd,
                              const float* __restrict__ trand,
                              float* __restrict__ out,
                              int n) {
    __shared__ float zsh[16 * MAX_PTS];

    int warp = threadIdx.x >> 5;
    int lane = threadIdx.x & 31;
    int r = (blockIdx.x << 4) + warp;
    if (r >= n) return;

    float ox = ro[3 * r + 0], oy = ro[3 * r + 1], oz = ro[3 * r + 2];
    float dx = rd[3 * r + 0], dy = rd[3 * r + 1], dz = rd[3 * r + 2];
    float near_v = g_eff_near[r];

    int j0 = lane << 2;
    float4 t4 = reinterpret_cast<const float4*>(trand + (size_t)r * MAX_PTS)[lane];
    float tr[4] = {t4.x, t4.y, t4.z, t4.w};

    // z_at for j0-1 .. j0+4 (za[0] unused when j0==0)
    float za[6];
#pragma unroll
    for (int m = 0; m < 6; m++) za[m] = z_at(near_v, j0 - 1 + m);

    float zv[4];
#pragma unroll
    for (int i = 0; i < 4; i++) {
        int j = j0 + i;
        float zj = za[i + 1];
        float lower = (j == 0)   ? zj : 0.5f * (za[i] + zj);
        float upper = (j == 127) ? zj : 0.5f * (zj + za[i + 2]);
        zv[i] = lower + (upper - lower) * tr[i];
    }

    size_t total = (size_t)n * MAX_PTS;
    float4 zq = make_float4(zv[0], zv[1], zv[2], zv[3]);
    reinterpret_cast<float4*>(out + total * 3)[(size_t)r * 32 + lane] = zq;
    reinterpret_cast<float4*>(zsh + warp * MAX_PTS)[lane] = zq;
    __syncwarp();

    const float* zw = zsh + warp * MAX_PTS;
    float4* pts4 = reinterpret_cast<float4*>(out) + (size_t)r * 96;
#pragma unroll
    for (int m = 0; m < 3; m++) {
        int f4 = (m << 5) + lane;
        int f0 = f4 << 2;
        float comp[4];
#pragma unroll
        for (int i = 0; i < 4; i++) {
            int f = f0 + i;
            int sidx = f / 3;
            int c = f - 3 * sidx;
            float z = zw[sidx];
            float o = (c == 0) ? ox : (c == 1) ? oy : oz;
            float d = (c == 0) ? dx : (c == 1) ? dy : dz;
            comp[i] = o + d * z;
        }
        pts4[f4] = make_float4(comp[0], comp[1], comp[2], comp[3]);
    }
}

// ---------------------------------------------------------------------------
extern "C" void kernel_launch(void* const* d_in, const int* in_sizes, int n_in,
                              void* d_out, int out_size) {
    const float*   ro  = (const float*)d_in[0];   // rays_o   [n,3]
    const float*   rd  = (const float*)d_in[1];   // viewdirs [n,3]
    const float*   tr  = (const float*)d_in[2];   // t_rand   [n,128]
    const uint8_t* occ = (const uint8_t*)d_in[3]; // occ_grid [128^3], 4B elems

    int n = in_sizes[0] / 3;

    setup_kernel<<<1, 1>>>();
    pack_occ_kernel<<<OCC_WORDS / 256, 256>>>(occ);
    march_kernel<<<(n + 255) / 256, 256>>>(ro, rd, n);
    sample_kernel<<<(n + 15) / 16, 512>>>(ro, rd, tr, (float*)d_out, n);
}

// round 6
// speedup vs baseline: 6.2544x; 1.3357x over previous
#include <cuda_runtime.h>
#include <cstdint>

#define MAX_PTS     128
#define GRID_R      128
#define OCC_WORDS   (GRID_R * GRID_R * GRID_R / 32)   // 65536 words = 256 KB
#define NSTEPS      200

__device__ uint32_t g_occ_bits[OCC_WORDS];
__device__ float    g_tn[NSTEPS];   // exact fp32 fold of t += STEP from 2.0

// ---------------------------------------------------------------------------
// Kernel 1: pack occupancy (4-byte elems, bit = word != 0) into bit grid.
// Thread (0,0) also builds the exact tn fold table (bit-identical to the
// reference's serial t += STEP chain; STEP = fp32(0.5*sqrt(27/16384)) exact).
// ---------------------------------------------------------------------------
__global__ void pack_occ_kernel(const uint8_t* __restrict__ occ) {
    if (blockIdx.x == 0 && threadIdx.x == 0) {
        const float STEP = 0.5f * __fsqrt_rn(0.00164794921875f);
        float t = 2.0f;
        for (int k = 0; k < NSTEPS; k++) { t = __fadd_rn(t, STEP); g_tn[k] = t; }
    }
    int w = blockIdx.x * blockDim.x + threadIdx.x;
    if (w >= OCC_WORDS) return;
    const uint4* p = reinterpret_cast<const uint4*>(occ) + (size_t)w * 8;
    uint32_t bits = 0;
#pragma unroll
    for (int i = 0; i < 8; i++) {
        uint4 v = p[i];
        if (v.x) bits |= 1u << (i * 4 + 0);
        if (v.y) bits |= 1u << (i * 4 + 1);
        if (v.z) bits |= 1u << (i * 4 + 2);
        if (v.w) bits |= 1u << (i * 4 + 3);
    }
    g_occ_bits[w] = bits;
}

// ---------------------------------------------------------------------------
// voxel index: trunc(RN(s/CELL)), CELL = 3*2^-7. RN(s/CELL) = RN(s/3)*128
// exactly; RN(s/3) via Markstein two-FMA -> correctly rounded, bit-identical
// to __fdiv_rn. (int) truncates toward zero (numpy astype): s in (-CELL,0)
// maps to idx 0 (VALID) -> box expanded by one CELL on negative faces.
// ---------------------------------------------------------------------------
__device__ __forceinline__ int vox_idx(float s) {
    const float THIRD = 0.33333334f;            // RN(1/3)
    float q0 = __fmul_rn(s, THIRD);
    float rr = __fmaf_rn(-3.0f, q0, s);
    float q  = __fmaf_rn(rr, THIRD, q0);
    return (int)__fmul_rn(q, 128.0f);
}

__device__ __forceinline__ float z_at(float near_v, int jj) {
    float t = (jj >= 127) ? 1.0f : (float)jj * (1.0f / 127.0f);
    return near_v * (1.0f - t) + 6.0f * t;
}

// ---------------------------------------------------------------------------
// Kernel 2: fused march + sample, one WARP per ray. 512-thr blocks (16 rays).
//
// March (step-parallel): lane u tests step k0+u; ballot resolves the earliest
// hit/past with hit-over-past precedence at the same step. Slab entry skip +
// exit early-out on the truncation-expanded box ((-1.5-CELL, 1.5) per axis),
// 3-step margins; reciprocals only on lanes 0-2 (3 MUFU/ray).
//
// Sample: lane owns samples 4l..4l+3 -> 12 contiguous pts floats, staged in
// smem as 3 float4 (stride-3 float4 across lanes: conflict-free per phase),
// then read back lane-consecutive and stored fully coalesced. z stored
// directly as coalesced float4 (no smem needed).
// ---------------------------------------------------------------------------
__global__ void __launch_bounds__(512) fused_kernel(
        const float* __restrict__ ro,
        const float* __restrict__ rd,
        const float* __restrict__ trand,
        float* __restrict__ out,
        int n) {
    __shared__ float  sTn[NSTEPS];
    __shared__ float4 psh[16 * 96];     // 24 KB pts staging

    for (int i = threadIdx.x; i < NSTEPS; i += blockDim.x) sTn[i] = g_tn[i];
    __syncthreads();

    int warp = threadIdx.x >> 5;
    int lane = threadIdx.x & 31;
    int r = (blockIdx.x << 4) + warp;
    if (r >= n) return;

    const float CELL = 0.0234375f;
    const float STEP = 0.5f * __fsqrt_rn(0.00164794921875f);
    const float INV_STEP = 49.267f;     // approx 1/STEP; 3-step margin absorbs
    const float BMIN = -1.5f - CELL;
    const float BMAX =  1.5f;

    float ox = ro[3 * r + 0], oy = ro[3 * r + 1], oz = ro[3 * r + 2];
    float dx = rd[3 * r + 0], dy = rd[3 * r + 1], dz = rd[3 * r + 2];

    // ---- slab test: lanes 0..2 handle one axis each, butterfly-reduce ----
    float tlo = 0.0f, thi = 1e30f;
    if (lane < 3) {
        float o = (lane == 0) ? ox : (lane == 1) ? oy : oz;
        float d = (lane == 0) ? dx : (lane == 1) ? dy : dz;
        if (fabsf(d) > 1e-8f) {
            float inv = __frcp_rn(d);
            float t1 = (BMIN - o) * inv;
            float t2 = (BMAX - o) * inv;
            tlo = fminf(t1, t2);
            thi = fmaxf(t1, t2);
        } else if (o < BMIN - 0.001f || o > BMAX + 0.001f) {
            tlo = 1e9f;    // parallel & strictly outside -> never valid
        }
    }
#pragma unroll
    for (int off = 16; off; off >>= 1) {
        tlo = fmaxf(tlo, __shfl_xor_sync(0xffffffffu, tlo, off));
        thi = fminf(thi, __shfl_xor_sync(0xffffffffu, thi, off));
    }
    tlo = fminf(tlo, 1e8f);
    int k_start = (int)floorf((tlo - 2.0f) * INV_STEP) - 3;
    k_start = max(k_start, 0);
    k_start = min(k_start, NSTEPS - 1);   // final chunk always contains a past
    float limit = fminf(6.0f, thi + 3.0f * STEP);

    // ---- step-parallel march ----
    float nn = 2.0f;
#pragma unroll 1
    for (int k0 = k_start; k0 < NSTEPS; k0 += 32) {
        int k = k0 + lane;
        float tn = (k < NSTEPS) ? sTn[k] : 1e9f;
        float sx = __fadd_rn(__fadd_rn(ox, __fmul_rn(dx, tn)), 1.5f);
        float sy = __fadd_rn(__fadd_rn(oy, __fmul_rn(dy, tn)), 1.5f);
        float sz = __fadd_rn(__fadd_rn(oz, __fmul_rn(dz, tn)), 1.5f);
        int jx = vox_idx(sx);
        int jy = vox_idx(sy);
        int jz = vox_idx(sz);
        bool valid = ((unsigned)jx < 128u) & ((unsigned)jy < 128u) &
                     ((unsigned)jz < 128u);
        bool hit = false;
        if (valid) {
            int li = (jx << 14) | (jy << 7) | jz;
            hit = (g_occ_bits[li >> 5] >> (li & 31)) & 1u;
        }
        bool past = (tn > limit);
        unsigned hm = __ballot_sync(0xffffffffu, hit);
        unsigned st = __ballot_sync(0xffffffffu, hit | past);
        if (st) {
            int b = __ffs(st) - 1;                    // earliest stopping step
            bool isHit = (hm >> b) & 1u;              // hit beats past there
            float tnb = __shfl_sync(0xffffffffu, tn, b);
            nn = isHit ? fminf(tnb, 6.0f) : 6.0f;
            break;
        }
    }
    float near_v = fminf(nn, 6.0f);

    // ---- stratified sampling: lane owns samples j0..j0+3 ----
    int j0 = lane << 2;
    float4 t4 = reinterpret_cast<const float4*>(trand + (size_t)r * MAX_PTS)[lane];
    float tr[4] = {t4.x, t4.y, t4.z, t4.w};

    float za[6];
#pragma unroll
    for (int m = 0; m < 6; m++) za[m] = z_at(near_v, j0 - 1 + m);

    float zv[4];
#pragma unroll
    for (int i = 0; i < 4; i++) {
        int j = j0 + i;
        float zj = za[i + 1];
        float lower = (j == 0)   ? zj : 0.5f * (za[i] + zj);
        float upper = (j == 127) ? zj : 0.5f * (zj + za[i + 2]);
        zv[i] = lower + (upper - lower) * tr[i];
    }

    size_t total = (size_t)n * MAX_PTS;
    reinterpret_cast<float4*>(out + total * 3)[(size_t)r * 32 + lane] =
        make_float4(zv[0], zv[1], zv[2], zv[3]);

    // 12 contiguous pts floats for samples j0..j0+3
    float p[12];
#pragma unroll
    for (int i = 0; i < 4; i++) {
        p[3 * i + 0] = ox + dx * zv[i];
        p[3 * i + 1] = oy + dy * zv[i];
        p[3 * i + 2] = oz + dz * zv[i];
    }
    float4* base = psh + warp * 96;
    base[3 * lane + 0] = make_float4(p[0], p[1], p[2],  p[3]);
    base[3 * lane + 1] = make_float4(p[4], p[5], p[6],  p[7]);
    base[3 * lane + 2] = make_float4(p[8], p[9], p[10], p[11]);
    __syncwarp();

    float4* pts4 = reinterpret_cast<float4*>(out) + (size_t)r * 96;
    pts4[lane +  0] = base[lane +  0];
    pts4[lane + 32] = base[lane + 32];
    pts4[lane + 64] = base[lane + 64];
}

// ---------------------------------------------------------------------------
extern "C" void kernel_launch(void* const* d_in, const int* in_sizes, int n_in,
                              void* d_out, int out_size) {
    const float*   ro  = (const float*)d_in[0];   // rays_o   [n,3]
    const float*   rd  = (const float*)d_in[1];   // viewdirs [n,3]
    const float*   tr  = (const float*)d_in[2];   // t_rand   [n,128]
    const uint8_t* occ = (const uint8_t*)d_in[3]; // occ_grid [128^3], 4B elems

    int n = in_sizes[0] / 3;

    pack_occ_kernel<<<OCC_WORDS / 256, 256>>>(occ);
    fused_kernel<<<(n + 15) / 16, 512>>>(ro, rd, tr, (float*)d_out, n);
}

// round 7
// speedup vs baseline: 7.5279x; 1.2036x over previous
#include <cuda_runtime.h>
#include <cstdint>

#define MAX_PTS     128
#define GRID_R      128
#define OCC_ELEMS   (GRID_R * GRID_R * GRID_R)        // 2097152
#define OCC_WORDS   (OCC_ELEMS / 32)                  // 65536 words = 256 KB
#define NSTEPS      200

__device__ uint32_t g_occ_bits[OCC_WORDS];
__device__ float    g_tn[NSTEPS];   // exact fp32 fold of t += STEP from 2.0

// ---------------------------------------------------------------------------
// Kernel 1: pack occupancy. One thread per element (coalesced 4B load),
// warp ballot assembles 32 bits, lane 0 stores the word. Thread (0,0) also
// builds the exact tn fold table (bit-identical to reference t += STEP).
// ---------------------------------------------------------------------------
__global__ void pack_occ_kernel(const uint32_t* __restrict__ occ) {
    if (blockIdx.x == 0 && threadIdx.x == 0) {
        const float STEP = 0.5f * __fsqrt_rn(0.00164794921875f);
        float t = 2.0f;
        for (int k = 0; k < NSTEPS; k++) { t = __fadd_rn(t, STEP); g_tn[k] = t; }
    }
    int e = blockIdx.x * blockDim.x + threadIdx.x;
    unsigned bit = (occ[e] != 0u);
    unsigned word = __ballot_sync(0xffffffffu, bit);
    if ((e & 31) == 0) g_occ_bits[e >> 5] = word;
}

// ---------------------------------------------------------------------------
// voxel index: trunc(RN(s/CELL)), CELL = 3*2^-7. RN(s/CELL) = RN(s/3)*128
// exactly; RN(s/3) via Markstein two-FMA -> correctly rounded, bit-identical
// to __fdiv_rn. (int) truncates toward zero (numpy astype): s in (-CELL,0)
// maps to idx 0 (VALID) -> box expanded by one CELL on negative faces.
// ---------------------------------------------------------------------------
__device__ __forceinline__ int vox_idx(float s) {
    const float THIRD = 0.33333334f;            // RN(1/3)
    float q0 = __fmul_rn(s, THIRD);
    float rr = __fmaf_rn(-3.0f, q0, s);
    float q  = __fmaf_rn(rr, THIRD, q0);
    return (int)__fmul_rn(q, 128.0f);
}

__device__ __forceinline__ float z_at(float near_v, int jj) {
    float t = (jj >= 127) ? 1.0f : (float)jj * (1.0f / 127.0f);
    return near_v * (1.0f - t) + 6.0f * t;
}

// ---------------------------------------------------------------------------
// Kernel 2: fused march + sample, one WARP per ray. 256-thr blocks (8 rays).
// t_rand float4 prefetched BEFORE the march so the march latency hides
// behind the load. No block-wide sync (tn table read straight from global,
// L1-resident). Outputs stored with streaming hint (__stcs).
// ---------------------------------------------------------------------------
__global__ void __launch_bounds__(256) fused_kernel(
        const float* __restrict__ ro,
        const float* __restrict__ rd,
        const float* __restrict__ trand,
        float* __restrict__ out,
        int n) {
    __shared__ float4 psh[8 * 96];      // 12 KB pts staging

    int warp = threadIdx.x >> 5;
    int lane = threadIdx.x & 31;
    int r = (blockIdx.x << 3) + warp;
    if (r >= n) return;

    const float CELL = 0.0234375f;
    const float STEP = 0.5f * __fsqrt_rn(0.00164794921875f);
    const float INV_STEP = 49.267f;     // approx 1/STEP; 3-step margin absorbs
    const float BMIN = -1.5f - CELL;    // truncation-expanded negative faces
    const float BMAX =  1.5f;

    // prefetch t_rand early: march latency hides behind this load
    float4 t4 = __ldcs(reinterpret_cast<const float4*>(trand + (size_t)r * MAX_PTS) + lane);

    float ox = ro[3 * r + 0], oy = ro[3 * r + 1], oz = ro[3 * r + 2];
    float dx = rd[3 * r + 0], dy = rd[3 * r + 1], dz = rd[3 * r + 2];

    // ---- slab test on expanded box: lanes 0..2, butterfly-reduce ----
    float tlo = 0.0f, thi = 1e30f;
    if (lane < 3) {
        float o = (lane == 0) ? ox : (lane == 1) ? oy : oz;
        float d = (lane == 0) ? dx : (lane == 1) ? dy : dz;
        if (fabsf(d) > 1e-8f) {
            float inv = __frcp_rn(d);
            float t1 = (BMIN - o) * inv;
            float t2 = (BMAX - o) * inv;
            tlo = fminf(t1, t2);
            thi = fmaxf(t1, t2);
        } else if (o < BMIN - 0.001f || o > BMAX + 0.001f) {
            tlo = 1e9f;    // parallel & strictly outside -> never valid
        }
    }
#pragma unroll
    for (int off = 16; off; off >>= 1) {
        tlo = fmaxf(tlo, __shfl_xor_sync(0xffffffffu, tlo, off));
        thi = fminf(thi, __shfl_xor_sync(0xffffffffu, thi, off));
    }
    tlo = fminf(tlo, 1e8f);
    int k_start = (int)floorf((tlo - 2.0f) * INV_STEP) - 3;
    k_start = max(k_start, 0);
    k_start = min(k_start, NSTEPS - 1);   // final chunk always contains a past
    float limit = fminf(6.0f, thi + 3.0f * STEP);

    // ---- step-parallel march: lane u probes step k0+u ----
    float nn = 2.0f;
#pragma unroll 1
    for (int k0 = k_start; k0 < NSTEPS; k0 += 32) {
        int k = k0 + lane;
        float tn = (k < NSTEPS) ? __ldg(&g_tn[k]) : 1e9f;
        float sx = __fadd_rn(__fadd_rn(ox, __fmul_rn(dx, tn)), 1.5f);
        float sy = __fadd_rn(__fadd_rn(oy, __fmul_rn(dy, tn)), 1.5f);
        float sz = __fadd_rn(__fadd_rn(oz, __fmul_rn(dz, tn)), 1.5f);
        int jx = vox_idx(sx);
        int jy = vox_idx(sy);
        int jz = vox_idx(sz);
        bool valid = ((unsigned)jx < 128u) & ((unsigned)jy < 128u) &
                     ((unsigned)jz < 128u);
        bool hit = false;
        if (valid) {
            int li = (jx << 14) | (jy << 7) | jz;
            hit = (g_occ_bits[li >> 5] >> (li & 31)) & 1u;
        }
        bool past = (tn > limit);
        unsigned hm = __ballot_sync(0xffffffffu, hit);
        unsigned st = __ballot_sync(0xffffffffu, hit | past);
        if (st) {
            int b = __ffs(st) - 1;                    // earliest stopping step
            bool isHit = (hm >> b) & 1u;              // hit beats past there
            float tnb = __shfl_sync(0xffffffffu, tn, b);
            nn = isHit ? fminf(tnb, 6.0f) : 6.0f;
            break;
        }
    }
    float near_v = fminf(nn, 6.0f);

    // ---- stratified sampling: lane owns samples j0..j0+3 ----
    int j0 = lane << 2;
    float tr[4] = {t4.x, t4.y, t4.z, t4.w};

    float za[6];
#pragma unroll
    for (int m = 0; m < 6; m++) za[m] = z_at(near_v, j0 - 1 + m);

    float zv[4];
#pragma unroll
    for (int i = 0; i < 4; i++) {
        int j = j0 + i;
        float zj = za[i + 1];
        float lower = (j == 0)   ? zj : 0.5f * (za[i] + zj);
        float upper = (j == 127) ? zj : 0.5f * (zj + za[i + 2]);
        zv[i] = lower + (upper - lower) * tr[i];
    }

    size_t total = (size_t)n * MAX_PTS;
    __stcs(reinterpret_cast<float4*>(out + total * 3) + (size_t)r * 32 + lane,
           make_float4(zv[0], zv[1], zv[2], zv[3]));

    // 12 contiguous pts floats for samples j0..j0+3, staged through smem
    float p[12];
#pragma unroll
    for (int i = 0; i < 4; i++) {
        p[3 * i + 0] = ox + dx * zv[i];
        p[3 * i + 1] = oy + dy * zv[i];
        p[3 * i + 2] = oz + dz * zv[i];
    }
    float4* base = psh + warp * 96;
    base[3 * lane + 0] = make_float4(p[0], p[1], p[2],  p[3]);
    base[3 * lane + 1] = make_float4(p[4], p[5], p[6],  p[7]);
    base[3 * lane + 2] = make_float4(p[8], p[9], p[10], p[11]);
    __syncwarp();

    float4* pts4 = reinterpret_cast<float4*>(out) + (size_t)r * 96;
    __stcs(pts4 + lane +  0, base[lane +  0]);
    __stcs(pts4 + lane + 32, base[lane + 32]);
    __stcs(pts4 + lane + 64, base[lane + 64]);
}

// ---------------------------------------------------------------------------
extern "C" void kernel_launch(void* const* d_in, const int* in_sizes, int n_in,
                              void* d_out, int out_size) {
    const float*    ro  = (const float*)d_in[0];    // rays_o   [n,3]
    const float*    rd  = (const float*)d_in[1];    // viewdirs [n,3]
    const float*    tr  = (const float*)d_in[2];    // t_rand   [n,128]
    const uint32_t* occ = (const uint32_t*)d_in[3]; // occ_grid [128^3], 4B elems

    int n = in_sizes[0] / 3;

    pack_occ_kernel<<<OCC_ELEMS / 256, 256>>>(occ);
    fused_kernel<<<(n + 7) / 8, 256>>>(ro, rd, tr, (float*)d_out, n);
}

// round 8
// speedup vs baseline: 7.8362x; 1.0410x over previous
#include <cuda_runtime.h>
#include <cstdint>

#define MAX_PTS     128
#define GRID_R      128
#define OCC_ELEMS   (GRID_R * GRID_R * GRID_R)        // 2097152
#define OCC_WORDS   (OCC_ELEMS / 32)                  // 65536 words = 256 KB
#define NSTEPS      200

__device__ uint32_t g_occ_bits[OCC_WORDS];
__device__ float    g_tn[NSTEPS];   // exact fp32 fold of t += STEP from 2.0

// ---------------------------------------------------------------------------
// Kernel 1: pack occupancy. Thread loads uint4 (4 elems) -> 4-bit nibble;
// 8-lane subgroups assemble a 32-bit word via __reduce_or_sync. Thread (0,0)
// also builds the exact tn fold table (bit-identical to reference t += STEP;
// STEP = fp32(0.5*sqrt(27/16384)) exact).
// ---------------------------------------------------------------------------
__global__ void pack_occ_kernel(const uint4* __restrict__ occ) {
    if (blockIdx.x == 0 && threadIdx.x == 0) {
        const float STEP = 0.5f * __fsqrt_rn(0.00164794921875f);
        float t = 2.0f;
        for (int k = 0; k < NSTEPS; k++) { t = __fadd_rn(t, STEP); g_tn[k] = t; }
    }
    int e = blockIdx.x * blockDim.x + threadIdx.x;    // one uint4 = 4 elems
    uint4 v = occ[e];
    unsigned nib = (v.x != 0u) | ((v.y != 0u) << 1) |
                   ((v.z != 0u) << 2) | ((v.w != 0u) << 3);
    int lane = threadIdx.x & 31;
    unsigned submask = 0xffu << (8 * (lane >> 3));
    unsigned word = __reduce_or_sync(submask, nib << (4 * (lane & 7)));
    if ((lane & 7) == 0) g_occ_bits[e >> 3] = word;
}

// ---------------------------------------------------------------------------
// voxel index: trunc(RN(s/CELL)), CELL = 3*2^-7. RN(s/CELL) = RN(s/3)*128
// exactly; RN(s/3) via Markstein two-FMA -> correctly rounded, bit-identical
// to __fdiv_rn. (int) truncates toward zero (numpy astype): s in (-CELL,0)
// maps to idx 0 (VALID) -> box expanded by one CELL on negative faces.
// ---------------------------------------------------------------------------
__device__ __forceinline__ int vox_idx(float s) {
    const float THIRD = 0.33333334f;            // RN(1/3)
    float q0 = __fmul_rn(s, THIRD);
    float rr = __fmaf_rn(-3.0f, q0, s);
    float q  = __fmaf_rn(rr, THIRD, q0);
    return (int)__fmul_rn(q, 128.0f);
}

// ---------------------------------------------------------------------------
// Kernel 2: fused march + sample, one WARP per ray. 256-thr blocks (8 rays).
//
// March: step-parallel with ballot (bit-exact decisions: fold table + exact
// divide + expanded-box slab with 3-step margins).
//
// Sample: z_vals are LINEAR in near -> z = near + (6-near)*c with
//   c = (j-0.5+tr)/127 interior, tr*(0.5/127) at j=0, (126.5+0.5tr)/127 at 127
// and pts = (o+d*near) + d*(6-near)*c. 2 ops per z, 1 fma per pts component.
// ---------------------------------------------------------------------------
__global__ void __launch_bounds__(256) fused_kernel(
        const float* __restrict__ ro,
        const float* __restrict__ rd,
        const float* __restrict__ trand,
        float* __restrict__ out,
        int n) {
    __shared__ float4 psh[8 * 96];      // 12 KB pts staging

    int warp = threadIdx.x >> 5;
    int lane = threadIdx.x & 31;
    int r = (blockIdx.x << 3) + warp;
    if (r >= n) return;

    const float CELL = 0.0234375f;
    const float STEP = 0.5f * __fsqrt_rn(0.00164794921875f);
    const float INV_STEP = 49.267f;     // approx 1/STEP; 3-step margin absorbs
    const float BMIN = -1.5f - CELL;    // truncation-expanded negative faces
    const float BMAX =  1.5f;
    const float INV127 = 0.007874016f;  // RN(1/127)

    // prefetch t_rand early: march latency hides behind this load
    float4 t4 = __ldcs(reinterpret_cast<const float4*>(trand + (size_t)r * MAX_PTS) + lane);

    float ox = ro[3 * r + 0], oy = ro[3 * r + 1], oz = ro[3 * r + 2];
    float dx = rd[3 * r + 0], dy = rd[3 * r + 1], dz = rd[3 * r + 2];

    // ---- slab test on expanded box: lanes 0..2, butterfly-reduce ----
    float tlo = 0.0f, thi = 1e30f;
    if (lane < 3) {
        float o = (lane == 0) ? ox : (lane == 1) ? oy : oz;
        float d = (lane == 0) ? dx : (lane == 1) ? dy : dz;
        if (fabsf(d) > 1e-8f) {
            float inv = __frcp_rn(d);
            float t1 = (BMIN - o) * inv;
            float t2 = (BMAX - o) * inv;
            tlo = fminf(t1, t2);
            thi = fmaxf(t1, t2);
        } else if (o < BMIN - 0.001f || o > BMAX + 0.001f) {
            tlo = 1e9f;    // parallel & strictly outside -> never valid
        }
    }
#pragma unroll
    for (int off = 16; off; off >>= 1) {
        tlo = fmaxf(tlo, __shfl_xor_sync(0xffffffffu, tlo, off));
        thi = fminf(thi, __shfl_xor_sync(0xffffffffu, thi, off));
    }
    tlo = fminf(tlo, 1e8f);
    int k_start = (int)floorf((tlo - 2.0f) * INV_STEP) - 3;
    k_start = max(k_start, 0);
    k_start = min(k_start, NSTEPS - 1);   // final chunk always contains a past
    float limit = fminf(6.0f, thi + 3.0f * STEP);

    // ---- step-parallel march: lane u probes step k0+u ----
    float nn = 2.0f;
#pragma unroll 1
    for (int k0 = k_start; k0 < NSTEPS; k0 += 32) {
        int k = k0 + lane;
        float tn = (k < NSTEPS) ? __ldg(&g_tn[k]) : 1e9f;
        float sx = __fadd_rn(__fadd_rn(ox, __fmul_rn(dx, tn)), 1.5f);
        float sy = __fadd_rn(__fadd_rn(oy, __fmul_rn(dy, tn)), 1.5f);
        float sz = __fadd_rn(__fadd_rn(oz, __fmul_rn(dz, tn)), 1.5f);
        int jx = vox_idx(sx);
        int jy = vox_idx(sy);
        int jz = vox_idx(sz);
        bool valid = ((unsigned)jx < 128u) & ((unsigned)jy < 128u) &
                     ((unsigned)jz < 128u);
        bool hit = false;
        if (valid) {
            int li = (jx << 14) | (jy << 7) | jz;
            hit = (g_occ_bits[li >> 5] >> (li & 31)) & 1u;
        }
        bool past = (tn > limit);
        unsigned hm = __ballot_sync(0xffffffffu, hit);
        unsigned st = __ballot_sync(0xffffffffu, hit | past);
        if (st) {
            int b = __ffs(st) - 1;                    // earliest stopping step
            bool isHit = (hm >> b) & 1u;              // hit beats past there
            float tnb = __shfl_sync(0xffffffffu, tn, b);
            nn = isHit ? fminf(tnb, 6.0f) : 6.0f;
            break;
        }
    }
    float near_v = fminf(nn, 6.0f);

    // ---- stratified sampling: lane owns samples j0..j0+3 ----
    int j0 = lane << 2;
    float tr[4] = {t4.x, t4.y, t4.z, t4.w};

    float span = 6.0f - near_v;
    float bx = __fmaf_rn(dx, near_v, ox), ex = dx * span;
    float by = __fmaf_rn(dy, near_v, oy), ey = dy * span;
    float bz = __fmaf_rn(dz, near_v, oz), ez = dz * span;

    float c[4], zv[4];
#pragma unroll
    for (int i = 0; i < 4; i++) {
        int j = j0 + i;
        float ci;
        if (j == 0)        ci = tr[i] * (0.5f * INV127);
        else if (j == 127) ci = __fmaf_rn(tr[i], 0.5f, 126.5f) * INV127;
        else               ci = (tr[i] + ((float)j - 0.5f)) * INV127;
        c[i] = ci;
        zv[i] = __fmaf_rn(span, ci, near_v);
    }

    size_t total = (size_t)n * MAX_PTS;
    __stcs(reinterpret_cast<float4*>(out + total * 3) + (size_t)r * 32 + lane,
           make_float4(zv[0], zv[1], zv[2], zv[3]));

    // 12 contiguous pts floats for samples j0..j0+3, staged through smem
    float p[12];
#pragma unroll
    for (int i = 0; i < 4; i++) {
        p[3 * i + 0] = __fmaf_rn(ex, c[i], bx);
        p[3 * i + 1] = __fmaf_rn(ey, c[i], by);
        p[3 * i + 2] = __fmaf_rn(ez, c[i], bz);
    }
    float4* base = psh + warp * 96;
    base[3 * lane + 0] = make_float4(p[0], p[1], p[2],  p[3]);
    base[3 * lane + 1] = make_float4(p[4], p[5], p[6],  p[7]);
    base[3 * lane + 2] = make_float4(p[8], p[9], p[10], p[11]);
    __syncwarp();

    float4* pts4 = reinterpret_cast<float4*>(out) + (size_t)r * 96;
    __stcs(pts4 + lane +  0, base[lane +  0]);
    __stcs(pts4 + lane + 32, base[lane + 32]);
    __stcs(pts4 + lane + 64, base[lane + 64]);
}

// ---------------------------------------------------------------------------
extern "C" void kernel_launch(void* const* d_in, const int* in_sizes, int n_in,
                              void* d_out, int out_size) {
    const float* ro  = (const float*)d_in[0];    // rays_o   [n,3]
    const float* rd  = (const float*)d_in[1];    // viewdirs [n,3]
    const float* tr  = (const float*)d_in[2];    // t_rand   [n,128]
    const uint4* occ = (const uint4*)d_in[3];    // occ_grid [128^3], 4B elems

    int n = in_sizes[0] / 3;

    pack_occ_kernel<<<OCC_ELEMS / 4 / 256, 256>>>(occ);
    fused_kernel<<<(n + 7) / 8, 256>>>(ro, rd, tr, (float*)d_out, n);
}